// round 4
// baseline (speedup 1.0000x reference)
#include <cuda_runtime.h>
#include <cuda_bf16.h>
#include <cstdint>

// Masked attention B=2 H=12 S=2048 D=64 fp32.
// FlashAttention-2 via mma.sync.m16n8k16 bf16 with hi/lo split (3 MMAs/GEMM).
// R4: ldmatrix.x4 fragment loads, Q fragments hoisted to registers, smem is a
// Q/(K,V) union (36.9KB). P stays in registers.

#define HN 12
#define SLEN 2048
#define DH 64
#define BQ 128
#define BK 64
#define NTH 256
#define NTILES (SLEN / BK)
#define PW 36                  // row pitch in words (144 B)
#define ROWB 144               // row pitch bytes
#define PLANE (64 * PW)        // one 64-row plane, words

// word offsets in dynamic smem (union: Q planes overlay K/V planes)
#define W_KH 0
#define W_KL (1 * PLANE)
#define W_VH (2 * PLANE)
#define W_VL (3 * PLANE)
#define W_QH 0                 // Q hi: rows 0..127 over KH+KL area
#define W_QL (2 * PLANE)       // Q lo: rows 0..127 over VH+VL area
#define SMEM_BYTES (4 * PLANE * 4)   // 36864

__device__ __forceinline__ uint32_t smem_u32(const void* p) {
    uint32_t a;
    asm("{ .reg .u64 t; cvta.to.shared.u64 t, %1; cvt.u32.u64 %0, t; }"
        : "=r"(a) : "l"(p));
    return a;
}
__device__ __forceinline__ uint32_t pack_bf(float lo, float hi) {
    uint32_t r;
    asm("cvt.rn.satfinite.bf16x2.f32 %0, %1, %2;" : "=r"(r) : "f"(hi), "f"(lo));
    return r;
}
__device__ __forceinline__ void mma_bf16(float* d,
                                         uint32_t a0, uint32_t a1, uint32_t a2, uint32_t a3,
                                         uint32_t b0, uint32_t b1) {
    asm volatile("mma.sync.aligned.m16n8k16.row.col.f32.bf16.bf16.f32 "
                 "{%0,%1,%2,%3},{%4,%5,%6,%7},{%8,%9},{%0,%1,%2,%3};"
                 : "+f"(d[0]), "+f"(d[1]), "+f"(d[2]), "+f"(d[3])
                 : "r"(a0), "r"(a1), "r"(a2), "r"(a3), "r"(b0), "r"(b1));
}
__device__ __forceinline__ void ldsm4(uint32_t& r0, uint32_t& r1,
                                      uint32_t& r2, uint32_t& r3, uint32_t addr) {
    asm volatile("ldmatrix.sync.aligned.m8n8.x4.shared.b16 {%0,%1,%2,%3}, [%4];"
                 : "=r"(r0), "=r"(r1), "=r"(r2), "=r"(r3) : "r"(addr));
}
__device__ __forceinline__ void split_store(uint32_t* WH, uint32_t* WL,
                                            int widx, float4 v) {
    uint32_t h0 = pack_bf(v.x, v.y);
    uint32_t h1 = pack_bf(v.z, v.w);
    float hx = __uint_as_float(h0 << 16), hy = __uint_as_float(h0 & 0xffff0000u);
    float hz = __uint_as_float(h1 << 16), hw = __uint_as_float(h1 & 0xffff0000u);
    uint32_t l0 = pack_bf(v.x - hx, v.y - hy);
    uint32_t l1 = pack_bf(v.z - hz, v.w - hw);
    *reinterpret_cast<uint2*>(WH + widx) = make_uint2(h0, h1);
    *reinterpret_cast<uint2*>(WL + widx) = make_uint2(l0, l1);
}

__global__ void __launch_bounds__(NTH, 2)
attn_mma_kernel(const float* __restrict__ Q, const float* __restrict__ K,
                const float* __restrict__ V, const int* __restrict__ M,
                float* __restrict__ O)
{
    extern __shared__ uint32_t smw[];
    const uint32_t smb = smem_u32(smw);

    const int tid  = threadIdx.x;
    const int lane = tid & 31;
    const int w    = tid >> 5;
    const int g    = lane >> 2;
    const int qd   = lane & 3;

    const int b  = blockIdx.z, h = blockIdx.y;
    const int q0 = blockIdx.x * BQ;
    const size_t bh = (size_t)b * HN + h;
    const float* Qb = Q + (bh * SLEN + q0) * DH;
    const float* Kb = K + bh * SLEN * DH;
    const float* Vb = V + bh * SLEN * DH;
    const int*   Mb = M + (size_t)b * SLEN * SLEN;

    // per-lane static ldmatrix offsets
    // A-type (Q): m0 rows+0 col+0, m1 rows+8 col+0, m2 rows+0 col+16, m3 rows+8 col+16
    const uint32_t offA = (uint32_t)(((lane & 7) + ((lane >> 3) & 1) * 8) * ROWB
                                     + (lane >> 4) * 16);
    // B-type (K/V): m0 rows+0 col+0, m1 rows+0 col+16, m2 rows+8 col+0, m3 rows+8 col+16
    const uint32_t offB = (uint32_t)(((lane & 7) + (lane >> 4) * 8) * ROWB
                                     + ((lane >> 3) & 1) * 16);

    // ---- prologue: Q -> smem hi/lo (union area), then hoist fragments ----
    {
        const int row = tid >> 1, c0 = (tid & 1) * 32;
        const float* src = Qb + (size_t)row * DH + c0;
#pragma unroll
        for (int i = 0; i < 8; i++) {
            float4 v = *reinterpret_cast<const float4*>(src + 4 * i);
            split_store(smw + W_QH, smw + W_QL, row * PW + ((c0 + 4 * i) >> 1), v);
        }
    }
    __syncthreads();

    uint32_t qh[4][4], ql[4][4];
    {
        const uint32_t qbase = smb + (uint32_t)(16 * w) * ROWB + offA;
#pragma unroll
        for (int kc = 0; kc < 4; kc++) {
            ldsm4(qh[kc][0], qh[kc][1], qh[kc][2], qh[kc][3], qbase + kc * 32);
            ldsm4(ql[kc][0], ql[kc][1], ql[kc][2], ql[kc][3],
                  qbase + kc * 32 + (uint32_t)(W_QL * 4));
        }
    }

    float s[8][4];
    float o[8][4] = {};
    float m0 = -1e30f, m1 = -1e30f, l0 = 0.0f, l1 = 0.0f;

    const int qrow = q0 + 16 * w + g;
    const int2* mp0 = reinterpret_cast<const int2*>(Mb + (size_t)qrow * SLEN);
    const int2* mp1 = reinterpret_cast<const int2*>(Mb + (size_t)(qrow + 8) * SLEN);

#pragma unroll 1
    for (int t = 0; t < NTILES; t++) {
        const int k0 = t * BK;

        __syncthreads();   // everyone done with previous K/V (and Q hoist)

        // ---- K tile -> smem hi/lo (rows = k, 64 x 64) ----
        {
            const int row = tid >> 2, c0 = (tid & 3) * 16;
            const float* src = Kb + (size_t)(k0 + row) * DH + c0;
#pragma unroll
            for (int i = 0; i < 4; i++) {
                float4 v = *reinterpret_cast<const float4*>(src + 4 * i);
                split_store(smw + W_KH, smw + W_KL, row * PW + ((c0 + 4 * i) >> 1), v);
            }
        }
        // ---- V tile -> smem transposed hi/lo (rows = d, cols = k) ----
        {
            const int kk = (tid & 31) * 2, d0 = (tid >> 5) * 8;
            const float* r0 = Vb + (size_t)(k0 + kk) * DH + d0;
            const float* r1 = r0 + DH;
            float va[8], vb[8];
            *reinterpret_cast<float4*>(va)     = *reinterpret_cast<const float4*>(r0);
            *reinterpret_cast<float4*>(va + 4) = *reinterpret_cast<const float4*>(r0 + 4);
            *reinterpret_cast<float4*>(vb)     = *reinterpret_cast<const float4*>(r1);
            *reinterpret_cast<float4*>(vb + 4) = *reinterpret_cast<const float4*>(r1 + 4);
#pragma unroll
            for (int dd = 0; dd < 8; dd++) {
                uint32_t hw = pack_bf(va[dd], vb[dd]);
                float ha = __uint_as_float(hw << 16);
                float hb = __uint_as_float(hw & 0xffff0000u);
                uint32_t lw = pack_bf(va[dd] - ha, vb[dd] - hb);
                const int widx = (d0 + dd) * PW + (kk >> 1);
                smw[W_VH + widx] = hw;
                smw[W_VL + widx] = lw;
            }
        }
        __syncthreads();

        // ---- MMA1: S = Qh*Kh + Qh*Kl + Ql*Kh ----
#pragma unroll
        for (int j = 0; j < 8; j++) { s[j][0] = s[j][1] = s[j][2] = s[j][3] = 0.0f; }
#pragma unroll
        for (int kc = 0; kc < 4; kc++) {
#pragma unroll
            for (int jp = 0; jp < 4; jp++) {
                const uint32_t ad = smb + (uint32_t)(jp * 16 * ROWB + kc * 32) + offB;
                uint32_t h0r, h1r, h2r, h3r, l0r, l1r, l2r, l3r;
                ldsm4(h0r, h1r, h2r, h3r, ad);                         // KH
                ldsm4(l0r, l1r, l2r, l3r, ad + (uint32_t)(W_KL * 4));  // KL
                mma_bf16(s[2 * jp],     qh[kc][0], qh[kc][1], qh[kc][2], qh[kc][3], h0r, h1r);
                mma_bf16(s[2 * jp],     qh[kc][0], qh[kc][1], qh[kc][2], qh[kc][3], l0r, l1r);
                mma_bf16(s[2 * jp],     ql[kc][0], ql[kc][1], ql[kc][2], ql[kc][3], h0r, h1r);
                mma_bf16(s[2 * jp + 1], qh[kc][0], qh[kc][1], qh[kc][2], qh[kc][3], h2r, h3r);
                mma_bf16(s[2 * jp + 1], qh[kc][0], qh[kc][1], qh[kc][2], qh[kc][3], l2r, l3r);
                mma_bf16(s[2 * jp + 1], ql[kc][0], ql[kc][1], ql[kc][2], ql[kc][3], h2r, h3r);
            }
        }

        // ---- mask + scale + online softmax (registers only) ----
        float mt0 = -1e30f, mt1 = -1e30f;
#pragma unroll
        for (int j = 0; j < 8; j++) {
            const int ci = (k0 + 8 * j) >> 1;
            int2 ma  = mp0[ci + qd];
            int2 mb2 = mp1[ci + qd];
            s[j][0] = ma.x  ? s[j][0] * 0.125f : -1e20f;
            s[j][1] = ma.y  ? s[j][1] * 0.125f : -1e20f;
            s[j][2] = mb2.x ? s[j][2] * 0.125f : -1e20f;
            s[j][3] = mb2.y ? s[j][3] * 0.125f : -1e20f;
            mt0 = fmaxf(mt0, fmaxf(s[j][0], s[j][1]));
            mt1 = fmaxf(mt1, fmaxf(s[j][2], s[j][3]));
        }
        mt0 = fmaxf(mt0, __shfl_xor_sync(0xffffffffu, mt0, 1));
        mt0 = fmaxf(mt0, __shfl_xor_sync(0xffffffffu, mt0, 2));
        mt1 = fmaxf(mt1, __shfl_xor_sync(0xffffffffu, mt1, 1));
        mt1 = fmaxf(mt1, __shfl_xor_sync(0xffffffffu, mt1, 2));

        const float mn0 = fmaxf(m0, mt0), mn1 = fmaxf(m1, mt1);
        const float c0f = __expf(m0 - mn0), c1f = __expf(m1 - mn1);
        m0 = mn0; m1 = mn1;

        float rs0 = 0.0f, rs1 = 0.0f;
#pragma unroll
        for (int j = 0; j < 8; j++) {
            s[j][0] = __expf(s[j][0] - mn0);
            s[j][1] = __expf(s[j][1] - mn0);
            s[j][2] = __expf(s[j][2] - mn1);
            s[j][3] = __expf(s[j][3] - mn1);
            rs0 += s[j][0] + s[j][1];
            rs1 += s[j][2] + s[j][3];
        }
        rs0 += __shfl_xor_sync(0xffffffffu, rs0, 1);
        rs0 += __shfl_xor_sync(0xffffffffu, rs0, 2);
        rs1 += __shfl_xor_sync(0xffffffffu, rs1, 1);
        rs1 += __shfl_xor_sync(0xffffffffu, rs1, 2);
        l0 = l0 * c0f + rs0;
        l1 = l1 * c1f + rs1;

#pragma unroll
        for (int j = 0; j < 8; j++) {
            o[j][0] *= c0f; o[j][1] *= c0f;
            o[j][2] *= c1f; o[j][3] *= c1f;
        }

        // ---- MMA2: O += Ph*Vh + Ph*Vl + Pl*Vh ----
#pragma unroll
        for (int kc = 0; kc < 4; kc++) {
            uint32_t ph0 = pack_bf(s[2 * kc][0], s[2 * kc][1]);
            uint32_t ph1 = pack_bf(s[2 * kc][2], s[2 * kc][3]);
            uint32_t ph2 = pack_bf(s[2 * kc + 1][0], s[2 * kc + 1][1]);
            uint32_t ph3 = pack_bf(s[2 * kc + 1][2], s[2 * kc + 1][3]);
            uint32_t pl0, pl1, pl2, pl3;
            {
                float a = __uint_as_float(ph0 << 16), bq = __uint_as_float(ph0 & 0xffff0000u);
                pl0 = pack_bf(s[2 * kc][0] - a, s[2 * kc][1] - bq);
                a = __uint_as_float(ph1 << 16); bq = __uint_as_float(ph1 & 0xffff0000u);
                pl1 = pack_bf(s[2 * kc][2] - a, s[2 * kc][3] - bq);
                a = __uint_as_float(ph2 << 16); bq = __uint_as_float(ph2 & 0xffff0000u);
                pl2 = pack_bf(s[2 * kc + 1][0] - a, s[2 * kc + 1][1] - bq);
                a = __uint_as_float(ph3 << 16); bq = __uint_as_float(ph3 & 0xffff0000u);
                pl3 = pack_bf(s[2 * kc + 1][2] - a, s[2 * kc + 1][3] - bq);
            }
#pragma unroll
            for (int jp = 0; jp < 4; jp++) {
                const uint32_t ad = smb + (uint32_t)(W_VH * 4 + jp * 16 * ROWB + kc * 32) + offB;
                uint32_t h0r, h1r, h2r, h3r, l0r, l1r, l2r, l3r;
                ldsm4(h0r, h1r, h2r, h3r, ad);                           // VH
                ldsm4(l0r, l1r, l2r, l3r, ad + (uint32_t)(PLANE * 4));   // VL
                mma_bf16(o[2 * jp],     ph0, ph1, ph2, ph3, h0r, h1r);
                mma_bf16(o[2 * jp],     ph0, ph1, ph2, ph3, l0r, l1r);
                mma_bf16(o[2 * jp],     pl0, pl1, pl2, pl3, h0r, h1r);
                mma_bf16(o[2 * jp + 1], ph0, ph1, ph2, ph3, h2r, h3r);
                mma_bf16(o[2 * jp + 1], ph0, ph1, ph2, ph3, l2r, l3r);
                mma_bf16(o[2 * jp + 1], pl0, pl1, pl2, pl3, h2r, h3r);
            }
        }
    }

    // ---- epilogue ----
    const float i0 = 1.0f / l0, i1 = 1.0f / l1;
    float* Ob0 = O + (bh * SLEN + qrow) * DH;
    float* Ob1 = Ob0 + 8 * DH;
#pragma unroll
    for (int j = 0; j < 8; j++) {
        const int cc = 8 * j + qd * 2;
        *reinterpret_cast<float2*>(Ob0 + cc) = make_float2(o[j][0] * i0, o[j][1] * i0);
        *reinterpret_cast<float2*>(Ob1 + cc) = make_float2(o[j][2] * i1, o[j][3] * i1);
    }
}

extern "C" void kernel_launch(void* const* d_in, const int* in_sizes, int n_in,
                              void* d_out, int out_size)
{
    const float* Q    = (const float*)d_in[0];
    const float* K    = (const float*)d_in[1];
    const float* V    = (const float*)d_in[2];
    const int*   mask = (const int*)d_in[3];
    float*       O    = (float*)d_out;

    cudaFuncSetAttribute(attn_mma_kernel,
                         cudaFuncAttributeMaxDynamicSharedMemorySize, SMEM_BYTES);

    dim3 grid(SLEN / BQ, HN, 2);   // 384 CTAs
    attn_mma_kernel<<<grid, NTH, SMEM_BYTES>>>(Q, K, V, mask, O);
}

// round 5
// speedup vs baseline: 1.1927x; 1.1927x over previous
#include <cuda_runtime.h>
#include <cuda_bf16.h>
#include <cstdint>

// Masked attention B=2 H=12 S=2048 D=64 fp32.
// R5: pre-pass converts Q/K/V to hi/lo bf16 planes (V transposed) and packs
// mask to bits. Main kernel: FlashAttention-2, mma.sync m16n8k16 bf16 with
// hi/lo split (3 MMAs/GEMM), 4 warps x 32 query rows (halves fragment
// traffic), cp.async double-buffered K/V tiles, register-resident P.

#define BATCH 2
#define HN 12
#define SLEN 2048
#define DH 64
#define BQ 128
#define BK 64
#define NTILES (SLEN / BK)
#define NTH 128

#define ROWB 144            // smem row pitch bytes (64 bf16 + 16B pad)
#define PLANEB 9216         // 64 rows * 144
#define BUFB (4 * PLANEB)   // KH,KL,VH,VL
#define SMEM_BYTES (2 * BUFB)   // 73728
#define QLOFF 18432         // Q-lo plane byte offset (prologue overlay)

#define NELEM (BATCH * HN * SLEN * DH)   // 6291456

// scratch: hi/lo bf16 planes + packed mask bits
__device__ __nv_bfloat16 g_QH[NELEM], g_QL[NELEM];
__device__ __nv_bfloat16 g_KH[NELEM], g_KL[NELEM];
__device__ __nv_bfloat16 g_VTH[NELEM], g_VTL[NELEM];   // [bh][d][k]
__device__ uint32_t g_MB[BATCH * SLEN * (SLEN / 32)];  // 1MB bitmask

__device__ __forceinline__ uint32_t smem_u32(const void* p) {
    uint32_t a;
    asm("{ .reg .u64 t; cvta.to.shared.u64 t, %1; cvt.u32.u64 %0, t; }"
        : "=r"(a) : "l"(p));
    return a;
}
__device__ __forceinline__ uint32_t pack_bf(float lo, float hi) {
    uint32_t r;
    asm("cvt.rn.satfinite.bf16x2.f32 %0, %1, %2;" : "=r"(r) : "f"(hi), "f"(lo));
    return r;
}
// split (a,b) -> hi word + residual-lo word
__device__ __forceinline__ uint2 split2(float a, float b) {
    uint32_t hw = pack_bf(a, b);
    float ha = __uint_as_float(hw << 16);
    float hb = __uint_as_float(hw & 0xffff0000u);
    return make_uint2(hw, pack_bf(a - ha, b - hb));
}
__device__ __forceinline__ void mma_bf16(float* d,
                                         uint32_t a0, uint32_t a1, uint32_t a2, uint32_t a3,
                                         uint32_t b0, uint32_t b1) {
    asm volatile("mma.sync.aligned.m16n8k16.row.col.f32.bf16.bf16.f32 "
                 "{%0,%1,%2,%3},{%4,%5,%6,%7},{%8,%9},{%0,%1,%2,%3};"
                 : "+f"(d[0]), "+f"(d[1]), "+f"(d[2]), "+f"(d[3])
                 : "r"(a0), "r"(a1), "r"(a2), "r"(a3), "r"(b0), "r"(b1));
}
__device__ __forceinline__ void ldsm4(uint32_t& r0, uint32_t& r1,
                                      uint32_t& r2, uint32_t& r3, uint32_t addr) {
    asm volatile("ldmatrix.sync.aligned.m8n8.x4.shared.b16 {%0,%1,%2,%3}, [%4];"
                 : "=r"(r0), "=r"(r1), "=r"(r2), "=r"(r3) : "r"(addr));
}
__device__ __forceinline__ void cp16(uint32_t dst, const void* src) {
    asm volatile("cp.async.cg.shared.global [%0], [%1], 16;"
                 :: "r"(dst), "l"(src) : "memory");
}
#define CP_COMMIT() asm volatile("cp.async.commit_group;" ::: "memory")
#define CP_WAIT0()  asm volatile("cp.async.wait_group 0;" ::: "memory")
#define CP_WAIT1()  asm volatile("cp.async.wait_group 1;" ::: "memory")

// ---------------- pre-pass kernels ----------------

__global__ void __launch_bounds__(256)
prep_qk(const float* __restrict__ Q, const float* __restrict__ K)
{
    const size_t i = ((size_t)blockIdx.x * 256 + threadIdx.x) * 4;
    float4 q = *reinterpret_cast<const float4*>(Q + i);
    uint2 a = split2(q.x, q.y), b = split2(q.z, q.w);
    *reinterpret_cast<uint2*>(&g_QH[i]) = make_uint2(a.x, b.x);
    *reinterpret_cast<uint2*>(&g_QL[i]) = make_uint2(a.y, b.y);
    float4 k = *reinterpret_cast<const float4*>(K + i);
    a = split2(k.x, k.y); b = split2(k.z, k.w);
    *reinterpret_cast<uint2*>(&g_KH[i]) = make_uint2(a.x, b.x);
    *reinterpret_cast<uint2*>(&g_KL[i]) = make_uint2(a.y, b.y);
}

__global__ void __launch_bounds__(256)
prep_vt(const float* __restrict__ V)
{
    __shared__ float vt[64][65];
    const int tid = threadIdx.x;
    const int bhh = blockIdx.y;
    const int k0 = blockIdx.x * 64;
    // load [k][d] coalesced, scatter to [d][k]
    {
        const int kk = tid >> 2, c0 = (tid & 3) * 16;
        const float* src = V + ((size_t)bhh * SLEN + k0 + kk) * DH + c0;
#pragma unroll
        for (int i = 0; i < 4; i++) {
            float4 v = *reinterpret_cast<const float4*>(src + 4 * i);
            vt[c0 + 4 * i + 0][kk] = v.x;
            vt[c0 + 4 * i + 1][kk] = v.y;
            vt[c0 + 4 * i + 2][kk] = v.z;
            vt[c0 + 4 * i + 3][kk] = v.w;
        }
    }
    __syncthreads();
    // write rows of Vt, hi/lo planes
    {
        const int d = tid >> 2, kc = (tid & 3) * 16;
        uint32_t hw[8], lw[8];
#pragma unroll
        for (int j = 0; j < 8; j++) {
            uint2 s2 = split2(vt[d][kc + 2 * j], vt[d][kc + 2 * j + 1]);
            hw[j] = s2.x; lw[j] = s2.y;
        }
        const size_t oi = ((size_t)bhh * DH + d) * SLEN + k0 + kc;
        *reinterpret_cast<uint4*>(&g_VTH[oi])     = make_uint4(hw[0], hw[1], hw[2], hw[3]);
        *reinterpret_cast<uint4*>(&g_VTH[oi + 8]) = make_uint4(hw[4], hw[5], hw[6], hw[7]);
        *reinterpret_cast<uint4*>(&g_VTL[oi])     = make_uint4(lw[0], lw[1], lw[2], lw[3]);
        *reinterpret_cast<uint4*>(&g_VTL[oi + 8]) = make_uint4(lw[4], lw[5], lw[6], lw[7]);
    }
}

__global__ void __launch_bounds__(256)
prep_mask(const int* __restrict__ M)
{
    const int wg = blockIdx.x * 8 + (threadIdx.x >> 5);
    const int lane = threadIdx.x & 31;
    int v = M[(size_t)wg * 32 + lane];
    uint32_t bits = __ballot_sync(0xffffffffu, v != 0);
    if (lane == 0) g_MB[wg] = bits;
}

// ---------------- main attention kernel ----------------

__global__ void __launch_bounds__(NTH, 2)
attn_mma_kernel(float* __restrict__ O)
{
    extern __shared__ uint32_t smw[];
    const uint32_t smb = smem_u32(smw);

    const int tid  = threadIdx.x;
    const int lane = tid & 31;
    const int w    = tid >> 5;          // warp 0..3, owns rows [32w,32w+32)
    const int g    = lane >> 2;
    const int qd   = lane & 3;

    const int b  = blockIdx.z, h = blockIdx.y;
    const int q0 = blockIdx.x * BQ;
    const int bh = b * HN + h;

    const uint32_t offA = (uint32_t)(((lane & 7) + ((lane >> 3) & 1) * 8) * ROWB
                                     + (lane >> 4) * 16);
    const uint32_t offB = (uint32_t)(((lane & 7) + (lane >> 4) * 8) * ROWB
                                     + ((lane >> 3) & 1) * 16);

    // ---- prologue: copy Q hi/lo planes into buf0 area, hoist fragments ----
    {
        const int row = (tid >> 3) & 127;   // with i below covers 128 rows x 2 planes
        const int col = tid & 7;
#pragma unroll
        for (int i = 0; i < 16; i++) {
            const int c = tid + NTH * i;
            const int plane = c >> 10;              // 0=QH 1=QL
            const int r2 = (c >> 3) & 127;
            const __nv_bfloat16* src = (plane ? g_QL : g_QH)
                + ((size_t)bh * SLEN + q0 + r2) * DH + col * 8;
            *reinterpret_cast<uint4*>(
                reinterpret_cast<char*>(smw) + plane * QLOFF + r2 * ROWB + col * 16)
                = *reinterpret_cast<const uint4*>(src);
        }
        (void)row;
    }
    __syncthreads();

    uint32_t qh[4][8], ql[4][8];
#pragma unroll
    for (int kc = 0; kc < 4; kc++) {
#pragma unroll
        for (int m = 0; m < 2; m++) {
            const uint32_t a = smb + (uint32_t)((32 * w + 16 * m) * ROWB + kc * 32) + offA;
            ldsm4(qh[kc][4 * m], qh[kc][4 * m + 1], qh[kc][4 * m + 2], qh[kc][4 * m + 3], a);
            ldsm4(ql[kc][4 * m], ql[kc][4 * m + 1], ql[kc][4 * m + 2], ql[kc][4 * m + 3],
                  a + QLOFF);
        }
    }
    __syncthreads();

    // mask row word pointers (4 rows per lane)
    const uint32_t* mrow[4];
#pragma unroll
    for (int r = 0; r < 4; r++)
        mrow[r] = g_MB + ((size_t)b * SLEN + q0 + 32 * w + g + 8 * r) * (SLEN / 32);

    const __nv_bfloat16* KHb = g_KH + (size_t)bh * SLEN * DH;
    const __nv_bfloat16* KLb = g_KL + (size_t)bh * SLEN * DH;
    const __nv_bfloat16* VHb = g_VTH + (size_t)bh * DH * SLEN;
    const __nv_bfloat16* VLb = g_VTL + (size_t)bh * DH * SLEN;

    // prefetch tile 0 into buffer 0
    {
        const int col = tid & 7;
#pragma unroll
        for (int i = 0; i < 16; i++) {
            const int p = i >> 2;
            const int row = (i & 3) * 16 + (tid >> 3);
            const __nv_bfloat16* src =
                (p == 0) ? KHb + (size_t)row * DH + col * 8 :
                (p == 1) ? KLb + (size_t)row * DH + col * 8 :
                (p == 2) ? VHb + (size_t)row * SLEN + col * 8 :
                           VLb + (size_t)row * SLEN + col * 8;
            cp16(smb + (uint32_t)(p * PLANEB + row * ROWB + col * 16), src);
        }
        CP_COMMIT();
    }

    float s[2][8][4];
    float o[2][8][4] = {};
    float mx[4] = {-1e30f, -1e30f, -1e30f, -1e30f};
    float ls[4] = {};

#pragma unroll 1
    for (int t = 0; t < NTILES; t++) {
        const int k0 = t * BK;
        const uint32_t bufc = smb + (uint32_t)((t & 1) * BUFB);

        // prefetch next tile
        if (t + 1 < NTILES) {
            const uint32_t bufn = smb + (uint32_t)(((t + 1) & 1) * BUFB);
            const int kn = (t + 1) * BK;
            const int col = tid & 7;
#pragma unroll
            for (int i = 0; i < 16; i++) {
                const int p = i >> 2;
                const int row = (i & 3) * 16 + (tid >> 3);
                const __nv_bfloat16* src =
                    (p == 0) ? KHb + (size_t)(kn + row) * DH + col * 8 :
                    (p == 1) ? KLb + (size_t)(kn + row) * DH + col * 8 :
                    (p == 2) ? VHb + (size_t)row * SLEN + kn + col * 8 :
                               VLb + (size_t)row * SLEN + kn + col * 8;
                cp16(bufn + (uint32_t)(p * PLANEB + row * ROWB + col * 16), src);
            }
            CP_COMMIT();
            CP_WAIT1();
        } else {
            CP_WAIT0();
        }

        // mask words for this tile
        uint32_t mw[4][2];
#pragma unroll
        for (int r = 0; r < 4; r++) {
            mw[r][0] = mrow[r][(k0 >> 5)];
            mw[r][1] = mrow[r][(k0 >> 5) + 1];
        }
        __syncthreads();

        // ---- MMA1: S = Qh*Kh + Qh*Kl + Ql*Kh ----
#pragma unroll
        for (int m = 0; m < 2; m++)
#pragma unroll
            for (int jn = 0; jn < 8; jn++)
#pragma unroll
                for (int e = 0; e < 4; e++) s[m][jn][e] = 0.0f;

#pragma unroll
        for (int kc = 0; kc < 4; kc++) {
#pragma unroll
            for (int jp = 0; jp < 4; jp++) {
                const uint32_t ad = bufc + (uint32_t)(jp * 16 * ROWB + kc * 32) + offB;
                uint32_t h0, h1, h2, h3, l0, l1, l2, l3;
                ldsm4(h0, h1, h2, h3, ad);
                ldsm4(l0, l1, l2, l3, ad + PLANEB);
#pragma unroll
                for (int m = 0; m < 2; m++) {
                    mma_bf16(s[m][2 * jp],     qh[kc][4 * m], qh[kc][4 * m + 1], qh[kc][4 * m + 2], qh[kc][4 * m + 3], h0, h1);
                    mma_bf16(s[m][2 * jp],     qh[kc][4 * m], qh[kc][4 * m + 1], qh[kc][4 * m + 2], qh[kc][4 * m + 3], l0, l1);
                    mma_bf16(s[m][2 * jp],     ql[kc][4 * m], ql[kc][4 * m + 1], ql[kc][4 * m + 2], ql[kc][4 * m + 3], h0, h1);
                    mma_bf16(s[m][2 * jp + 1], qh[kc][4 * m], qh[kc][4 * m + 1], qh[kc][4 * m + 2], qh[kc][4 * m + 3], h2, h3);
                    mma_bf16(s[m][2 * jp + 1], qh[kc][4 * m], qh[kc][4 * m + 1], qh[kc][4 * m + 2], qh[kc][4 * m + 3], l2, l3);
                    mma_bf16(s[m][2 * jp + 1], ql[kc][4 * m], ql[kc][4 * m + 1], ql[kc][4 * m + 2], ql[kc][4 * m + 3], h2, h3);
                }
            }
        }

        // ---- mask + scale + online softmax ----
        float mt[4] = {-1e30f, -1e30f, -1e30f, -1e30f};
#pragma unroll
        for (int r = 0; r < 4; r++) {
            const int m = r >> 1, lo2 = (r & 1) * 2;
#pragma unroll
            for (int jn = 0; jn < 8; jn++) {
                const uint32_t word = mw[r][jn >> 2];
                const int bp = (jn & 3) * 8 + 2 * qd;
                float x0 = ((word >> bp) & 1u)       ? s[m][jn][lo2]     * 0.125f : -1e20f;
                float x1 = ((word >> (bp + 1)) & 1u) ? s[m][jn][lo2 + 1] * 0.125f : -1e20f;
                s[m][jn][lo2] = x0; s[m][jn][lo2 + 1] = x1;
                mt[r] = fmaxf(mt[r], fmaxf(x0, x1));
            }
        }
#pragma unroll
        for (int r = 0; r < 4; r++) {
            mt[r] = fmaxf(mt[r], __shfl_xor_sync(0xffffffffu, mt[r], 1));
            mt[r] = fmaxf(mt[r], __shfl_xor_sync(0xffffffffu, mt[r], 2));
        }
        float corr[4];
#pragma unroll
        for (int r = 0; r < 4; r++) {
            const float mn = fmaxf(mx[r], mt[r]);
            corr[r] = __expf(mx[r] - mn);
            mx[r] = mn;
        }
        float rs[4] = {};
#pragma unroll
        for (int r = 0; r < 4; r++) {
            const int m = r >> 1, lo2 = (r & 1) * 2;
#pragma unroll
            for (int jn = 0; jn < 8; jn++) {
                float p0 = __expf(s[m][jn][lo2] - mx[r]);
                float p1 = __expf(s[m][jn][lo2 + 1] - mx[r]);
                s[m][jn][lo2] = p0; s[m][jn][lo2 + 1] = p1;
                rs[r] += p0 + p1;
            }
        }
#pragma unroll
        for (int r = 0; r < 4; r++) {
            rs[r] += __shfl_xor_sync(0xffffffffu, rs[r], 1);
            rs[r] += __shfl_xor_sync(0xffffffffu, rs[r], 2);
            ls[r] = ls[r] * corr[r] + rs[r];
        }
#pragma unroll
        for (int r = 0; r < 4; r++) {
            const int m = r >> 1, lo2 = (r & 1) * 2;
#pragma unroll
            for (int jn = 0; jn < 8; jn++) {
                o[m][jn][lo2]     *= corr[r];
                o[m][jn][lo2 + 1] *= corr[r];
            }
        }

        // ---- MMA2: O += Ph*Vh + Ph*Vl + Pl*Vh ----
#pragma unroll
        for (int kc = 0; kc < 4; kc++) {
            uint32_t ph[2][4], pl[2][4];
#pragma unroll
            for (int m = 0; m < 2; m++) {
                uint2 a0 = split2(s[m][2 * kc][0],     s[m][2 * kc][1]);
                uint2 a1 = split2(s[m][2 * kc][2],     s[m][2 * kc][3]);
                uint2 a2 = split2(s[m][2 * kc + 1][0], s[m][2 * kc + 1][1]);
                uint2 a3 = split2(s[m][2 * kc + 1][2], s[m][2 * kc + 1][3]);
                ph[m][0] = a0.x; ph[m][1] = a1.x; ph[m][2] = a2.x; ph[m][3] = a3.x;
                pl[m][0] = a0.y; pl[m][1] = a1.y; pl[m][2] = a2.y; pl[m][3] = a3.y;
            }
#pragma unroll
            for (int jp = 0; jp < 4; jp++) {
                const uint32_t ad = bufc + (uint32_t)(2 * PLANEB + jp * 16 * ROWB + kc * 32) + offB;
                uint32_t h0, h1, h2, h3, l0, l1, l2, l3;
                ldsm4(h0, h1, h2, h3, ad);
                ldsm4(l0, l1, l2, l3, ad + PLANEB);
#pragma unroll
                for (int m = 0; m < 2; m++) {
                    mma_bf16(o[m][2 * jp],     ph[m][0], ph[m][1], ph[m][2], ph[m][3], h0, h1);
                    mma_bf16(o[m][2 * jp],     ph[m][0], ph[m][1], ph[m][2], ph[m][3], l0, l1);
                    mma_bf16(o[m][2 * jp],     pl[m][0], pl[m][1], pl[m][2], pl[m][3], h0, h1);
                    mma_bf16(o[m][2 * jp + 1], ph[m][0], ph[m][1], ph[m][2], ph[m][3], h2, h3);
                    mma_bf16(o[m][2 * jp + 1], ph[m][0], ph[m][1], ph[m][2], ph[m][3], l2, l3);
                    mma_bf16(o[m][2 * jp + 1], pl[m][0], pl[m][1], pl[m][2], pl[m][3], h2, h3);
                }
            }
        }
        __syncthreads();
    }

    // ---- epilogue ----
#pragma unroll
    for (int r = 0; r < 4; r++) {
        const int m = r >> 1, lo2 = (r & 1) * 2;
        const float inv = 1.0f / ls[r];
        float* Ob = O + ((size_t)bh * SLEN + q0 + 32 * w + g + 8 * r) * DH;
#pragma unroll
        for (int jn = 0; jn < 8; jn++) {
            *reinterpret_cast<float2*>(Ob + 8 * jn + 2 * qd) =
                make_float2(o[m][jn][lo2] * inv, o[m][jn][lo2 + 1] * inv);
        }
    }
}

extern "C" void kernel_launch(void* const* d_in, const int* in_sizes, int n_in,
                              void* d_out, int out_size)
{
    const float* Q    = (const float*)d_in[0];
    const float* K    = (const float*)d_in[1];
    const float* V    = (const float*)d_in[2];
    const int*   mask = (const int*)d_in[3];
    float*       O    = (float*)d_out;

    prep_qk<<<NELEM / 1024, 256>>>(Q, K);
    prep_vt<<<dim3(SLEN / 64, BATCH * HN), 256>>>(V);
    prep_mask<<<(BATCH * SLEN * (SLEN / 32)) / 8, 256>>>(mask);

    cudaFuncSetAttribute(attn_mma_kernel,
                         cudaFuncAttributeMaxDynamicSharedMemorySize, SMEM_BYTES);
    dim3 grid(SLEN / BQ, HN, BATCH);   // 384 CTAs
    attn_mma_kernel<<<grid, NTH, SMEM_BYTES>>>(O);
}